// round 1
// baseline (speedup 1.0000x reference)
#include <cuda_runtime.h>
#include <cstddef>

#define NSEQ  2048
#define CDIM  64
#define CH    512
#define JD    4096          // 8 * 512
#define BTOT  16
#define ROWS_TOT (BTOT * NSEQ)   // 32768
#define EPS_F 1e-5f

// ---------------- scratch (device globals; no allocation allowed) ----------
__device__ float  g_Q[BTOT * NSEQ * CH];
__device__ float  g_K[BTOT * NSEQ * CH];
__device__ float  g_V[BTOT * NSEQ * CH];
__device__ float  g_S[(size_t)BTOT * CH * JD];     // scores -> attn (in place)
__device__ float  g_CTX[BTOT * NSEQ * CH];
__device__ double g_red[BTOT * 2];
__device__ float  g_rstd[BTOT];

// ============================================================================
// Generic NN SGEMM: C[M,N] = A[M,K] * B[K,N], row-major. Tiles 64x64x16,
// 256 threads, 4x4 per thread. K % 16 == 0, N % 64 == 0, M % 64 == 0.
// ============================================================================
__global__ void __launch_bounds__(256) gemm_nn(const float* __restrict__ A,
                                               const float* __restrict__ Bm,
                                               float* __restrict__ Cm,
                                               int M, int N, int K) {
    __shared__ __align__(16) float As[16][68];
    __shared__ __align__(16) float Bs[16][64];
    int bm = blockIdx.y * 64, bn = blockIdx.x * 64;
    int tid = threadIdx.x;
    int tx = tid & 15, ty = tid >> 4;

    int am = tid >> 2;              // 0..63
    int ak = (tid & 3) << 2;        // 0,4,8,12
    int br = tid >> 4;              // 0..15
    int bc = (tid & 15) << 2;       // 0..60

    const float* Aptr = A + (size_t)(bm + am) * K + ak;

    float acc[4][4];
#pragma unroll
    for (int i = 0; i < 4; i++)
#pragma unroll
        for (int j = 0; j < 4; j++) acc[i][j] = 0.f;

    for (int k0 = 0; k0 < K; k0 += 16) {
        float4 av = *(const float4*)(Aptr + k0);
        As[ak + 0][am] = av.x; As[ak + 1][am] = av.y;
        As[ak + 2][am] = av.z; As[ak + 3][am] = av.w;
        *(float4*)&Bs[br][bc] = *(const float4*)&Bm[(size_t)(k0 + br) * N + bn + bc];
        __syncthreads();
#pragma unroll
        for (int kk = 0; kk < 16; kk++) {
            float a0 = As[kk][ty * 4 + 0], a1 = As[kk][ty * 4 + 1];
            float a2 = As[kk][ty * 4 + 2], a3 = As[kk][ty * 4 + 3];
            float b0 = Bs[kk][tx * 4 + 0], b1 = Bs[kk][tx * 4 + 1];
            float b2 = Bs[kk][tx * 4 + 2], b3 = Bs[kk][tx * 4 + 3];
            acc[0][0] += a0 * b0; acc[0][1] += a0 * b1; acc[0][2] += a0 * b2; acc[0][3] += a0 * b3;
            acc[1][0] += a1 * b0; acc[1][1] += a1 * b1; acc[1][2] += a1 * b2; acc[1][3] += a1 * b3;
            acc[2][0] += a2 * b0; acc[2][1] += a2 * b1; acc[2][2] += a2 * b2; acc[2][3] += a2 * b3;
            acc[3][0] += a3 * b0; acc[3][1] += a3 * b1; acc[3][2] += a3 * b2; acc[3][3] += a3 * b3;
        }
        __syncthreads();
    }
#pragma unroll
    for (int i = 0; i < 4; i++) {
        float4 v = make_float4(acc[i][0], acc[i][1], acc[i][2], acc[i][3]);
        *(float4*)&Cm[(size_t)(bm + ty * 4 + i) * N + bn + tx * 4] = v;
    }
}

// ============================================================================
// scores GEMM (TN): S[ob][i][j] = sum_n Q[ob][n][i] * K[kvb][n][jc]
// ob = blockIdx.z (16), i-tile = blockIdx.y (4), j-tile = blockIdx.x (32).
// Tiles 128x128x16, 256 threads, 8x8 per thread.
// ============================================================================
__global__ void __launch_bounds__(256) scores_gemm() {
    int ob = blockIdx.z;
    int kvbase = (ob < 8) ? 8 : 0;
    int i0 = blockIdx.y << 7;
    int j0 = blockIdx.x << 7;
    int kvb = kvbase + (j0 >> 9);
    int jc0 = j0 & 511;

    const float* Aq = g_Q + (size_t)ob * NSEQ * CH;
    const float* Bk = g_K + (size_t)kvb * NSEQ * CH;

    __shared__ __align__(16) float As[16][128];
    __shared__ __align__(16) float Bs[16][128];

    int tid = threadIdx.x;
    int tx = tid & 15, ty = tid >> 4;
    int r1 = (tid * 4) >> 7;        // 0..7
    int c1 = (tid * 4) & 127;
    int r2 = r1 + 8;

    float acc[8][8];
#pragma unroll
    for (int i = 0; i < 8; i++)
#pragma unroll
        for (int j = 0; j < 8; j++) acc[i][j] = 0.f;

    for (int n0 = 0; n0 < NSEQ; n0 += 16) {
        *(float4*)&As[r1][c1] = *(const float4*)&Aq[(size_t)(n0 + r1) * CH + i0 + c1];
        *(float4*)&As[r2][c1] = *(const float4*)&Aq[(size_t)(n0 + r2) * CH + i0 + c1];
        *(float4*)&Bs[r1][c1] = *(const float4*)&Bk[(size_t)(n0 + r1) * CH + jc0 + c1];
        *(float4*)&Bs[r2][c1] = *(const float4*)&Bk[(size_t)(n0 + r2) * CH + jc0 + c1];
        __syncthreads();
#pragma unroll
        for (int kk = 0; kk < 16; kk++) {
            float a[8], b[8];
            *(float4*)&a[0] = *(float4*)&As[kk][ty * 8];
            *(float4*)&a[4] = *(float4*)&As[kk][ty * 8 + 4];
            *(float4*)&b[0] = *(float4*)&Bs[kk][tx * 8];
            *(float4*)&b[4] = *(float4*)&Bs[kk][tx * 8 + 4];
#pragma unroll
            for (int i = 0; i < 8; i++)
#pragma unroll
                for (int j = 0; j < 8; j++) acc[i][j] += a[i] * b[j];
        }
        __syncthreads();
    }
    float* outp = g_S + (size_t)ob * CH * JD;
#pragma unroll
    for (int i = 0; i < 8; i++) {
        size_t base = (size_t)(i0 + ty * 8 + i) * JD + j0 + tx * 8;
        *(float4*)&outp[base + 0] = make_float4(acc[i][0], acc[i][1], acc[i][2], acc[i][3]);
        *(float4*)&outp[base + 4] = make_float4(acc[i][4], acc[i][5], acc[i][6], acc[i][7]);
    }
}

// ============================================================================
// ctx GEMM (NT): CTX[ob][n][i] = sum_j attn[ob][i][j] * V[kvb(j)][n][jc]
// ob = blockIdx.z (16), n-tile = blockIdx.y (16), i-tile = blockIdx.x (4).
// Tiles 128x128x16, 256 threads, 8x8 per thread. Transposed smem loads.
// ============================================================================
__global__ void __launch_bounds__(256) ctx_gemm() {
    int ob = blockIdx.z;
    int kvbase = (ob < 8) ? 8 : 0;
    int n0 = blockIdx.y << 7;
    int i0 = blockIdx.x << 7;

    const float* attn = g_S + (size_t)ob * CH * JD;

    __shared__ __align__(16) float As[16][132];   // As[k][m] = vcat[n0+m][j0+k]
    __shared__ __align__(16) float Bs[16][132];   // Bs[k][n] = attn[i0+n][j0+k]

    int tid = threadIdx.x;
    int tx = tid & 15, ty = tid >> 4;
    int lm = tid >> 2;              // 0..63
    int lk = (tid & 3) << 2;        // 0,4,8,12

    float acc[8][8];
#pragma unroll
    for (int i = 0; i < 8; i++)
#pragma unroll
        for (int j = 0; j < 8; j++) acc[i][j] = 0.f;

    for (int j0 = 0; j0 < JD; j0 += 16) {
        int kvb = kvbase + (j0 >> 9);
        int jc0 = j0 & 511;
        const float* Vb = g_V + (size_t)kvb * NSEQ * CH;

        float4 v0 = *(const float4*)&Vb[(size_t)(n0 + lm) * CH + jc0 + lk];
        float4 v1 = *(const float4*)&Vb[(size_t)(n0 + lm + 64) * CH + jc0 + lk];
        As[lk + 0][lm] = v0.x; As[lk + 1][lm] = v0.y; As[lk + 2][lm] = v0.z; As[lk + 3][lm] = v0.w;
        As[lk + 0][lm + 64] = v1.x; As[lk + 1][lm + 64] = v1.y;
        As[lk + 2][lm + 64] = v1.z; As[lk + 3][lm + 64] = v1.w;

        float4 b0 = *(const float4*)&attn[(size_t)(i0 + lm) * JD + j0 + lk];
        float4 b1 = *(const float4*)&attn[(size_t)(i0 + lm + 64) * JD + j0 + lk];
        Bs[lk + 0][lm] = b0.x; Bs[lk + 1][lm] = b0.y; Bs[lk + 2][lm] = b0.z; Bs[lk + 3][lm] = b0.w;
        Bs[lk + 0][lm + 64] = b1.x; Bs[lk + 1][lm + 64] = b1.y;
        Bs[lk + 2][lm + 64] = b1.z; Bs[lk + 3][lm + 64] = b1.w;
        __syncthreads();
#pragma unroll
        for (int kk = 0; kk < 16; kk++) {
            float a[8], b[8];
            *(float4*)&a[0] = *(float4*)&As[kk][ty * 8];
            *(float4*)&a[4] = *(float4*)&As[kk][ty * 8 + 4];
            *(float4*)&b[0] = *(float4*)&Bs[kk][tx * 8];
            *(float4*)&b[4] = *(float4*)&Bs[kk][tx * 8 + 4];
#pragma unroll
            for (int i = 0; i < 8; i++)
#pragma unroll
                for (int j = 0; j < 8; j++) acc[i][j] += a[i] * b[j];
        }
        __syncthreads();
    }
    float* outp = g_CTX + (size_t)ob * NSEQ * CH;
#pragma unroll
    for (int i = 0; i < 8; i++) {
        size_t base = (size_t)(n0 + ty * 8 + i) * CH + i0 + tx * 8;
        *(float4*)&outp[base + 0] = make_float4(acc[i][0], acc[i][1], acc[i][2], acc[i][3]);
        *(float4*)&outp[base + 4] = make_float4(acc[i][4], acc[i][5], acc[i][6], acc[i][7]);
    }
}

// ============================================================================
// InstanceNorm statistics: sum / sumsq per batch over [512, 4096] plane.
// ============================================================================
__global__ void zero_red_k() {
    int t = threadIdx.x;
    if (t < BTOT) { g_red[2 * t] = 0.0; g_red[2 * t + 1] = 0.0; }
}

__global__ void __launch_bounds__(256) reduce_ss_k() {
    int b = blockIdx.x;
    int chunk = blockIdx.y;
    const float* p = g_S + (size_t)b * CH * JD + (size_t)chunk * 32768;
    double s = 0.0, s2 = 0.0;
    for (int i = threadIdx.x * 4; i < 32768; i += 1024) {
        float4 v = *(const float4*)&p[i];
        s  += (double)v.x + (double)v.y + (double)v.z + (double)v.w;
        s2 += (double)v.x * v.x + (double)v.y * v.y
            + (double)v.z * v.z + (double)v.w * v.w;
    }
    // warp reduce
    for (int off = 16; off > 0; off >>= 1) {
        s  += __shfl_down_sync(0xffffffffu, s, off);
        s2 += __shfl_down_sync(0xffffffffu, s2, off);
    }
    __shared__ double ws[8], ws2[8];
    int lane = threadIdx.x & 31, wid = threadIdx.x >> 5;
    if (lane == 0) { ws[wid] = s; ws2[wid] = s2; }
    __syncthreads();
    if (threadIdx.x == 0) {
        double ts = 0.0, ts2 = 0.0;
        for (int w = 0; w < 8; w++) { ts += ws[w]; ts2 += ws2[w]; }
        atomicAdd(&g_red[2 * b], ts);
        atomicAdd(&g_red[2 * b + 1], ts2);
    }
}

__global__ void finalize_k() {
    int t = threadIdx.x;
    if (t < BTOT) {
        double n = (double)CH * (double)JD;
        double mean = g_red[2 * t] / n;
        double var  = g_red[2 * t + 1] / n - mean * mean;
        g_rstd[t] = rsqrtf((float)var + EPS_F);
    }
}

// ============================================================================
// Fused scale + softmax over j (4096) per (b,i) row, in place in g_S.
// Mean shift cancels in softmax; only rstd scaling matters.
// ============================================================================
__global__ void __launch_bounds__(256) softmax_k() {
    int row = blockIdx.x;            // 0..8191
    int b = row >> 9;
    float rstd = g_rstd[b];
    float* p = g_S + (size_t)row * JD;
    int t = threadIdx.x;

    float x[16];
    float mx = -1e30f;
#pragma unroll
    for (int u = 0; u < 16; u++) {
        x[u] = p[u * 256 + t] * rstd;
        mx = fmaxf(mx, x[u]);
    }
    __shared__ float red[8];
    for (int off = 16; off > 0; off >>= 1)
        mx = fmaxf(mx, __shfl_xor_sync(0xffffffffu, mx, off));
    int lane = t & 31, wid = t >> 5;
    if (lane == 0) red[wid] = mx;
    __syncthreads();
    float gm = red[0];
#pragma unroll
    for (int w = 1; w < 8; w++) gm = fmaxf(gm, red[w]);
    __syncthreads();

    float sum = 0.f;
#pragma unroll
    for (int u = 0; u < 16; u++) {
        x[u] = __expf(x[u] - gm);
        sum += x[u];
    }
    for (int off = 16; off > 0; off >>= 1)
        sum += __shfl_xor_sync(0xffffffffu, sum, off);
    if (lane == 0) red[wid] = sum;
    __syncthreads();
    float tot = 0.f;
#pragma unroll
    for (int w = 0; w < 8; w++) tot += red[w];
    float inv = 1.0f / tot;
#pragma unroll
    for (int u = 0; u < 16; u++) p[u * 256 + t] = x[u] * inv;
}

// ============================================================================
// launch
// ============================================================================
extern "C" void kernel_launch(void* const* d_in, const int* in_sizes, int n_in,
                              void* d_out, int out_size) {
    const float* emb = (const float*)d_in[0];   // [16, 2048, 64]
    const float* Wq  = (const float*)d_in[1];   // [64, 512]
    const float* Wk  = (const float*)d_in[2];
    const float* Wv  = (const float*)d_in[3];
    const float* Wo  = (const float*)d_in[4];   // [512, 64]
    float* outp = (float*)d_out;                // [16, 2048, 64]

    void *qp, *kp, *vp, *cp;
    cudaGetSymbolAddress(&qp, g_Q);
    cudaGetSymbolAddress(&kp, g_K);
    cudaGetSymbolAddress(&vp, g_V);
    cudaGetSymbolAddress(&cp, g_CTX);

    // 1) projections: [32768,64] x [64,512]
    dim3 gproj(CH / 64, ROWS_TOT / 64);
    gemm_nn<<<gproj, 256>>>(emb, Wq, (float*)qp, ROWS_TOT, CH, CDIM);
    gemm_nn<<<gproj, 256>>>(emb, Wk, (float*)kp, ROWS_TOT, CH, CDIM);
    gemm_nn<<<gproj, 256>>>(emb, Wv, (float*)vp, ROWS_TOT, CH, CDIM);

    // 2) scores
    scores_gemm<<<dim3(JD / 128, CH / 128, BTOT), 256>>>();

    // 3) instance-norm stats -> rstd
    zero_red_k<<<1, 32>>>();
    reduce_ss_k<<<dim3(BTOT, 64), 256>>>();
    finalize_k<<<1, 32>>>();

    // 4) scale + softmax (in place)
    softmax_k<<<BTOT * CH, 256>>>();

    // 5) ctx
    ctx_gemm<<<dim3(CH / 128, NSEQ / 128, BTOT), 256>>>();

    // 6) out projection: [32768,512] x [512,64]
    gemm_nn<<<dim3(CDIM / 64, ROWS_TOT / 64), 256>>>((const float*)cp, Wo, outp,
                                                     ROWS_TOT, CDIM, CH);
}

// round 3
// speedup vs baseline: 2.3567x; 2.3567x over previous
#include <cuda_runtime.h>
#include <cuda_bf16.h>
#include <cstdint>
#include <cstddef>

#define NSEQ  2048
#define CDIM  64
#define CH    512
#define JD    4096
#define BTOT  16
#define ROWS_TOT (BTOT * NSEQ)
#define EPS_F 1e-5f

// 3 pipeline stages x (4 tiles of 128x32 bf16 = 8KB each) = 96KB
#define STAGE_BYTES 32768
#define SMEM_DYN (3 * STAGE_BYTES)

// ---------------- scratch ----------------
__device__ __nv_bfloat16 g_QtH[(size_t)BTOT * CH * NSEQ];   // [b][i][n]
__device__ __nv_bfloat16 g_QtL[(size_t)BTOT * CH * NSEQ];
__device__ __nv_bfloat16 g_KtH[(size_t)BTOT * CH * NSEQ];   // [b][j][n]
__device__ __nv_bfloat16 g_KtL[(size_t)BTOT * CH * NSEQ];
__device__ __nv_bfloat16 g_VH[(size_t)BTOT * NSEQ * CH];    // [b][n][c]
__device__ __nv_bfloat16 g_VL[(size_t)BTOT * NSEQ * CH];
__device__ float         g_S[(size_t)BTOT * CH * JD];
__device__ __nv_bfloat16 g_AH[(size_t)BTOT * CH * JD];      // attn hi [b][i][j]
__device__ __nv_bfloat16 g_AL[(size_t)BTOT * CH * JD];
__device__ float         g_CTX[(size_t)BTOT * NSEQ * CH];
__device__ double        g_red[BTOT * 2];
__device__ float         g_rstd[BTOT];

// ---------------- helpers ----------------
__device__ __forceinline__ uint32_t smem_u32(const void* p) {
    uint32_t a;
    asm("{ .reg .u64 t; cvta.to.shared.u64 t, %1; cvt.u32.u64 %0, t; }" : "=r"(a) : "l"(p));
    return a;
}
__device__ __forceinline__ void cp_async16(uint32_t s, const void* g) {
    asm volatile("cp.async.cg.shared.global [%0], [%1], 16;" :: "r"(s), "l"(g) : "memory");
}
__device__ __forceinline__ void cp_commit() {
    asm volatile("cp.async.commit_group;" ::: "memory");
}
template <int N>
__device__ __forceinline__ void cp_wait_group() {
    asm volatile("cp.async.wait_group %0;" :: "n"(N) : "memory");
}
__device__ __forceinline__ uint32_t swz(uint32_t off) {
    return off ^ ((off >> 3) & 0x30);
}
__device__ __forceinline__ uint32_t lds32(const char* base, uint32_t off) {
    return *(const uint32_t*)(base + swz(off));
}
__device__ __forceinline__ void mma16816(float* c, const uint32_t a[4],
                                         uint32_t b0, uint32_t b1) {
    asm volatile(
        "mma.sync.aligned.m16n8k16.row.col.f32.bf16.bf16.f32 "
        "{%0,%1,%2,%3}, {%4,%5,%6,%7}, {%8,%9}, {%0,%1,%2,%3};"
        : "+f"(c[0]), "+f"(c[1]), "+f"(c[2]), "+f"(c[3])
        : "r"(a[0]), "r"(a[1]), "r"(a[2]), "r"(a[3]), "r"(b0), "r"(b1));
}

// load one 128x32 bf16 tile (64B rows) into SW64-swizzled smem
__device__ __forceinline__ void ldtile(uint32_t sdst, const char* g, size_t stride, int tid) {
#pragma unroll
    for (int t = 0; t < 2; t++) {
        int op = tid + t * 256;
        int row = op >> 2, c = op & 3;
        uint32_t off = row * 64 + c * 16;
        cp_async16(sdst + swz(off), g + (size_t)row * stride + c * 16);
    }
}

// ============================================================================
// core split-bf16 mma.sync compute for one stage (two k16 steps)
// ============================================================================
__device__ __forceinline__ void compute_stage(const char* stage, int wm, int wn,
                                              int g, int tg, float acc[4][4][4]) {
    const char* Ah = stage;
    const char* Al = stage + 8192;
    const char* Bh = stage + 16384;
    const char* Bl = stage + 24576;
#pragma unroll
    for (int kk2 = 0; kk2 < 2; kk2++) {
        int kb = kk2 * 32 + tg * 4;
        uint32_t ah[4][4], al[4][4];
#pragma unroll
        for (int mt = 0; mt < 4; mt++) {
            uint32_t r0 = (uint32_t)(wm + mt * 16 + g) * 64;
            uint32_t r1 = r0 + 8 * 64;
            ah[mt][0] = lds32(Ah, r0 + kb);      ah[mt][1] = lds32(Ah, r1 + kb);
            ah[mt][2] = lds32(Ah, r0 + kb + 16); ah[mt][3] = lds32(Ah, r1 + kb + 16);
            al[mt][0] = lds32(Al, r0 + kb);      al[mt][1] = lds32(Al, r1 + kb);
            al[mt][2] = lds32(Al, r0 + kb + 16); al[mt][3] = lds32(Al, r1 + kb + 16);
        }
#pragma unroll
        for (int nt = 0; nt < 4; nt++) {
            uint32_t rb = (uint32_t)(wn + nt * 8 + g) * 64;
            uint32_t bh0 = lds32(Bh, rb + kb), bh1 = lds32(Bh, rb + kb + 16);
            uint32_t bl0 = lds32(Bl, rb + kb), bl1 = lds32(Bl, rb + kb + 16);
#pragma unroll
            for (int mt = 0; mt < 4; mt++) {
                mma16816(acc[mt][nt], ah[mt], bh0, bh1);
                mma16816(acc[mt][nt], al[mt], bh0, bh1);
                mma16816(acc[mt][nt], ah[mt], bl0, bl1);
            }
        }
    }
}

// ============================================================================
// scores: S[ob][i][j] = sum_n Qt[ob][i][n] * Kt[kvb][jc][n]
// grid (32, 4, 16), block 256
// ============================================================================
__global__ void __launch_bounds__(256, 1) scores_mma() {
    extern __shared__ char dsm[];
    uint32_t sb = smem_u32(dsm);

    int ob = blockIdx.z;
    int kvbase = (ob < 8) ? 8 : 0;
    int i0 = blockIdx.y << 7;
    int j0 = blockIdx.x << 7;
    int kvb = kvbase + (j0 >> 9);
    int jc0 = j0 & 511;

    int tid = threadIdx.x;
    int wid = tid >> 5, lane = tid & 31;
    int g = lane >> 2, tg = lane & 3;
    int wm = (wid >> 2) * 64, wn = (wid & 3) * 32;

    const char* AhB = (const char*)g_QtH + ((size_t)ob * CH + i0) * NSEQ * 2;
    const char* AlB = (const char*)g_QtL + ((size_t)ob * CH + i0) * NSEQ * 2;
    const char* BhB = (const char*)g_KtH + ((size_t)kvb * CH + jc0) * NSEQ * 2;
    const char* BlB = (const char*)g_KtL + ((size_t)kvb * CH + jc0) * NSEQ * 2;
    const size_t st = NSEQ * 2;

    float acc[4][4][4];
#pragma unroll
    for (int a = 0; a < 4; a++)
#pragma unroll
        for (int b = 0; b < 4; b++)
#pragma unroll
            for (int c = 0; c < 4; c++) acc[a][b][c] = 0.f;

    const int NCH = NSEQ / 32;   // 64

    auto load_chunk = [&](int c, int stg) {
        uint32_t s = sb + stg * STAGE_BYTES;
        size_t ko = (size_t)c * 64;
        ldtile(s,         AhB + ko, st, tid);
        ldtile(s + 8192,  AlB + ko, st, tid);
        ldtile(s + 16384, BhB + ko, st, tid);
        ldtile(s + 24576, BlB + ko, st, tid);
        cp_commit();
    };

    load_chunk(0, 0);
    load_chunk(1, 1);
    for (int c = 0; c < NCH; c++) {
        if (c + 2 < NCH) { load_chunk(c + 2, (c + 2) % 3); cp_wait_group<2>(); }
        else if (c + 1 < NCH) cp_wait_group<1>();
        else cp_wait_group<0>();
        __syncthreads();
        compute_stage(dsm + (c % 3) * STAGE_BYTES, wm, wn, g, tg, acc);
        __syncthreads();
    }

    float* gout = g_S + (size_t)ob * CH * JD;
#pragma unroll
    for (int mt = 0; mt < 4; mt++) {
#pragma unroll
        for (int nt = 0; nt < 4; nt++) {
            int row = i0 + wm + mt * 16 + g;
            int col = j0 + wn + nt * 8 + tg * 2;
            *(float2*)&gout[(size_t)row * JD + col] =
                make_float2(acc[mt][nt][0], acc[mt][nt][1]);
            *(float2*)&gout[(size_t)(row + 8) * JD + col] =
                make_float2(acc[mt][nt][2], acc[mt][nt][3]);
        }
    }
}

// ============================================================================
// ctx: CTX[ob][n][i] = sum_j V[kvb(j)][n][jc] * attn[ob][i][j]
// grid (4, 16, 16), block 256
// ============================================================================
__global__ void __launch_bounds__(256, 1) ctx_mma() {
    extern __shared__ char dsm[];
    uint32_t sb = smem_u32(dsm);

    int ob = blockIdx.z;
    int kvbase = (ob < 8) ? 8 : 0;
    int i0 = blockIdx.x << 7;
    int n0 = blockIdx.y << 7;

    int tid = threadIdx.x;
    int wid = tid >> 5, lane = tid & 31;
    int g = lane >> 2, tg = lane & 3;
    int wm = (wid >> 2) * 64, wn = (wid & 3) * 32;

    const char* BhB = (const char*)g_AH + ((size_t)ob * CH + i0) * JD * 2;
    const char* BlB = (const char*)g_AL + ((size_t)ob * CH + i0) * JD * 2;

    float acc[4][4][4];
#pragma unroll
    for (int a = 0; a < 4; a++)
#pragma unroll
        for (int b = 0; b < 4; b++)
#pragma unroll
            for (int c = 0; c < 4; c++) acc[a][b][c] = 0.f;

    const int NCH = JD / 32;   // 128

    auto load_chunk = [&](int c, int stg) {
        uint32_t s = sb + stg * STAGE_BYTES;
        int j0c = c * 32;
        int kvb = kvbase + (j0c >> 9);
        int jc0 = j0c & 511;
        const char* Ahp = (const char*)g_VH + (((size_t)kvb * NSEQ + n0) * CH + jc0) * 2;
        const char* Alp = (const char*)g_VL + (((size_t)kvb * NSEQ + n0) * CH + jc0) * 2;
        ldtile(s,         Ahp, CH * 2, tid);
        ldtile(s + 8192,  Alp, CH * 2, tid);
        ldtile(s + 16384, BhB + (size_t)j0c * 2, JD * 2, tid);
        ldtile(s + 24576, BlB + (size_t)j0c * 2, JD * 2, tid);
        cp_commit();
    };

    load_chunk(0, 0);
    load_chunk(1, 1);
    for (int c = 0; c < NCH; c++) {
        if (c + 2 < NCH) { load_chunk(c + 2, (c + 2) % 3); cp_wait_group<2>(); }
        else if (c + 1 < NCH) cp_wait_group<1>();
        else cp_wait_group<0>();
        __syncthreads();
        compute_stage(dsm + (c % 3) * STAGE_BYTES, wm, wn, g, tg, acc);
        __syncthreads();
    }

    float* gout = g_CTX + (size_t)ob * NSEQ * CH;
#pragma unroll
    for (int mt = 0; mt < 4; mt++) {
#pragma unroll
        for (int nt = 0; nt < 4; nt++) {
            int row = n0 + wm + mt * 16 + g;
            int col = i0 + wn + nt * 8 + tg * 2;
            *(float2*)&gout[(size_t)row * CH + col] =
                make_float2(acc[mt][nt][0], acc[mt][nt][1]);
            *(float2*)&gout[(size_t)(row + 8) * CH + col] =
                make_float2(acc[mt][nt][2], acc[mt][nt][3]);
        }
    }
}

// ============================================================================
// projection GEMM: C = A[32768,64] @ B[64,512]; epilogue splits to bf16 hi/lo.
// transposed=1 -> out[b][col][n], else out[m][col].
// ============================================================================
__global__ void __launch_bounds__(256) proj_gemm(const float* __restrict__ A,
                                                 const float* __restrict__ Bm,
                                                 __nv_bfloat16* __restrict__ OH,
                                                 __nv_bfloat16* __restrict__ OL,
                                                 int transposed) {
    __shared__ __align__(16) float As[16][68];
    __shared__ __align__(16) float Bs[16][64];
    const int K = CDIM, N = CH;
    int bm = blockIdx.y * 64, bn = blockIdx.x * 64;
    int tid = threadIdx.x;
    int tx = tid & 15, ty = tid >> 4;
    int am = tid >> 2, ak = (tid & 3) << 2;
    int br = tid >> 4, bc = (tid & 15) << 2;
    const float* Aptr = A + (size_t)(bm + am) * K + ak;

    float acc[4][4];
#pragma unroll
    for (int i = 0; i < 4; i++)
#pragma unroll
        for (int j = 0; j < 4; j++) acc[i][j] = 0.f;

    for (int k0 = 0; k0 < K; k0 += 16) {
        float4 av = *(const float4*)(Aptr + k0);
        As[ak + 0][am] = av.x; As[ak + 1][am] = av.y;
        As[ak + 2][am] = av.z; As[ak + 3][am] = av.w;
        *(float4*)&Bs[br][bc] = *(const float4*)&Bm[(size_t)(k0 + br) * N + bn + bc];
        __syncthreads();
#pragma unroll
        for (int kk = 0; kk < 16; kk++) {
            float a0 = As[kk][ty * 4 + 0], a1 = As[kk][ty * 4 + 1];
            float a2 = As[kk][ty * 4 + 2], a3 = As[kk][ty * 4 + 3];
            float b0 = Bs[kk][tx * 4 + 0], b1 = Bs[kk][tx * 4 + 1];
            float b2 = Bs[kk][tx * 4 + 2], b3 = Bs[kk][tx * 4 + 3];
            acc[0][0] += a0 * b0; acc[0][1] += a0 * b1; acc[0][2] += a0 * b2; acc[0][3] += a0 * b3;
            acc[1][0] += a1 * b0; acc[1][1] += a1 * b1; acc[1][2] += a1 * b2; acc[1][3] += a1 * b3;
            acc[2][0] += a2 * b0; acc[2][1] += a2 * b1; acc[2][2] += a2 * b2; acc[2][3] += a2 * b3;
            acc[3][0] += a3 * b0; acc[3][1] += a3 * b1; acc[3][2] += a3 * b2; acc[3][3] += a3 * b3;
        }
        __syncthreads();
    }

    if (transposed) {
        int b = bm >> 11;
        int nloc = (bm & 2047) + ty * 4;
#pragma unroll
        for (int j = 0; j < 4; j++) {
            int col = bn + tx * 4 + j;
            union { __nv_bfloat16 v[4]; uint2 u; } ph, pl;
#pragma unroll
            for (int i = 0; i < 4; i++) {
                float f = acc[i][j];
                __nv_bfloat16 h = __float2bfloat16(f);
                ph.v[i] = h;
                pl.v[i] = __float2bfloat16(f - __bfloat162float(h));
            }
            size_t off = (size_t)b * (CH * NSEQ) + (size_t)col * NSEQ + nloc;
            *(uint2*)&OH[off] = ph.u;
            *(uint2*)&OL[off] = pl.u;
        }
    } else {
#pragma unroll
        for (int i = 0; i < 4; i++) {
            int m = bm + ty * 4 + i;
            union { __nv_bfloat16 v[4]; uint2 u; } ph, pl;
#pragma unroll
            for (int j = 0; j < 4; j++) {
                float f = acc[i][j];
                __nv_bfloat16 h = __float2bfloat16(f);
                ph.v[j] = h;
                pl.v[j] = __float2bfloat16(f - __bfloat162float(h));
            }
            size_t off = (size_t)m * CH + bn + tx * 4;
            *(uint2*)&OH[off] = ph.u;
            *(uint2*)&OL[off] = pl.u;
        }
    }
}

// ============================================================================
// fp32 NN GEMM (out projection)
// ============================================================================
__global__ void __launch_bounds__(256) gemm_nn(const float* __restrict__ A,
                                               const float* __restrict__ Bm,
                                               float* __restrict__ Cm,
                                               int M, int N, int K) {
    __shared__ __align__(16) float As[16][68];
    __shared__ __align__(16) float Bs[16][64];
    int bm = blockIdx.y * 64, bn = blockIdx.x * 64;
    int tid = threadIdx.x;
    int tx = tid & 15, ty = tid >> 4;
    int am = tid >> 2, ak = (tid & 3) << 2;
    int br = tid >> 4, bc = (tid & 15) << 2;
    const float* Aptr = A + (size_t)(bm + am) * K + ak;

    float acc[4][4];
#pragma unroll
    for (int i = 0; i < 4; i++)
#pragma unroll
        for (int j = 0; j < 4; j++) acc[i][j] = 0.f;

    for (int k0 = 0; k0 < K; k0 += 16) {
        float4 av = *(const float4*)(Aptr + k0);
        As[ak + 0][am] = av.x; As[ak + 1][am] = av.y;
        As[ak + 2][am] = av.z; As[ak + 3][am] = av.w;
        *(float4*)&Bs[br][bc] = *(const float4*)&Bm[(size_t)(k0 + br) * N + bn + bc];
        __syncthreads();
#pragma unroll
        for (int kk = 0; kk < 16; kk++) {
            float a0 = As[kk][ty * 4 + 0], a1 = As[kk][ty * 4 + 1];
            float a2 = As[kk][ty * 4 + 2], a3 = As[kk][ty * 4 + 3];
            float b0 = Bs[kk][tx * 4 + 0], b1 = Bs[kk][tx * 4 + 1];
            float b2 = Bs[kk][tx * 4 + 2], b3 = Bs[kk][tx * 4 + 3];
            acc[0][0] += a0 * b0; acc[0][1] += a0 * b1; acc[0][2] += a0 * b2; acc[0][3] += a0 * b3;
            acc[1][0] += a1 * b0; acc[1][1] += a1 * b1; acc[1][2] += a1 * b2; acc[1][3] += a1 * b3;
            acc[2][0] += a2 * b0; acc[2][1] += a2 * b1; acc[2][2] += a2 * b2; acc[2][3] += a2 * b3;
            acc[3][0] += a3 * b0; acc[3][1] += a3 * b1; acc[3][2] += a3 * b2; acc[3][3] += a3 * b3;
        }
        __syncthreads();
    }
#pragma unroll
    for (int i = 0; i < 4; i++) {
        float4 v = make_float4(acc[i][0], acc[i][1], acc[i][2], acc[i][3]);
        *(float4*)&Cm[(size_t)(bm + ty * 4 + i) * N + bn + tx * 4] = v;
    }
}

// ============================================================================
// instance-norm stats + softmax
// ============================================================================
__global__ void zero_red_k() {
    int t = threadIdx.x;
    if (t < BTOT) { g_red[2 * t] = 0.0; g_red[2 * t + 1] = 0.0; }
}

__global__ void __launch_bounds__(256) reduce_ss_k() {
    int b = blockIdx.x;
    int chunk = blockIdx.y;
    const float* p = g_S + (size_t)b * CH * JD + (size_t)chunk * 32768;
    double s = 0.0, s2 = 0.0;
    for (int i = threadIdx.x * 4; i < 32768; i += 1024) {
        float4 v = *(const float4*)&p[i];
        s  += (double)v.x + (double)v.y + (double)v.z + (double)v.w;
        s2 += (double)v.x * v.x + (double)v.y * v.y
            + (double)v.z * v.z + (double)v.w * v.w;
    }
    for (int off = 16; off > 0; off >>= 1) {
        s  += __shfl_down_sync(0xffffffffu, s, off);
        s2 += __shfl_down_sync(0xffffffffu, s2, off);
    }
    __shared__ double ws[8], ws2[8];
    int lane = threadIdx.x & 31, wid = threadIdx.x >> 5;
    if (lane == 0) { ws[wid] = s; ws2[wid] = s2; }
    __syncthreads();
    if (threadIdx.x == 0) {
        double ts = 0.0, ts2 = 0.0;
        for (int w = 0; w < 8; w++) { ts += ws[w]; ts2 += ws2[w]; }
        atomicAdd(&g_red[2 * b], ts);
        atomicAdd(&g_red[2 * b + 1], ts2);
    }
}

__global__ void finalize_k() {
    int t = threadIdx.x;
    if (t < BTOT) {
        double n = (double)CH * (double)JD;
        double mean = g_red[2 * t] / n;
        double var  = g_red[2 * t + 1] / n - mean * mean;
        g_rstd[t] = rsqrtf((float)var + EPS_F);
    }
}

__global__ void __launch_bounds__(256) softmax_k() {
    int row = blockIdx.x;
    int b = row >> 9;
    float rstd = g_rstd[b];
    const float* p = g_S + (size_t)row * JD;
    __nv_bfloat16* ah = g_AH + (size_t)row * JD;
    __nv_bfloat16* al = g_AL + (size_t)row * JD;
    int t = threadIdx.x;

    float x[16];
    float mx = -1e30f;
#pragma unroll
    for (int u = 0; u < 16; u++) {
        x[u] = p[u * 256 + t] * rstd;
        mx = fmaxf(mx, x[u]);
    }
    __shared__ float red[8];
    for (int off = 16; off > 0; off >>= 1)
        mx = fmaxf(mx, __shfl_xor_sync(0xffffffffu, mx, off));
    int lane = t & 31, wid = t >> 5;
    if (lane == 0) red[wid] = mx;
    __syncthreads();
    float gm = red[0];
#pragma unroll
    for (int w = 1; w < 8; w++) gm = fmaxf(gm, red[w]);
    __syncthreads();

    float sum = 0.f;
#pragma unroll
    for (int u = 0; u < 16; u++) {
        x[u] = __expf(x[u] - gm);
        sum += x[u];
    }
    for (int off = 16; off > 0; off >>= 1)
        sum += __shfl_xor_sync(0xffffffffu, sum, off);
    if (lane == 0) red[wid] = sum;
    __syncthreads();
    float tot = 0.f;
#pragma unroll
    for (int w = 0; w < 8; w++) tot += red[w];
    float inv = 1.0f / tot;
#pragma unroll
    for (int u = 0; u < 16; u++) {
        float f = x[u] * inv;
        __nv_bfloat16 h = __float2bfloat16(f);
        ah[u * 256 + t] = h;
        al[u * 256 + t] = __float2bfloat16(f - __bfloat162float(h));
    }
}

// ============================================================================
// launch
// ============================================================================
extern "C" void kernel_launch(void* const* d_in, const int* in_sizes, int n_in,
                              void* d_out, int out_size) {
    const float* emb = (const float*)d_in[0];
    const float* Wq  = (const float*)d_in[1];
    const float* Wk  = (const float*)d_in[2];
    const float* Wv  = (const float*)d_in[3];
    const float* Wo  = (const float*)d_in[4];
    float* outp = (float*)d_out;

    void *qh, *ql, *kh, *kl, *vh, *vl, *cx;
    cudaGetSymbolAddress(&qh, g_QtH);
    cudaGetSymbolAddress(&ql, g_QtL);
    cudaGetSymbolAddress(&kh, g_KtH);
    cudaGetSymbolAddress(&kl, g_KtL);
    cudaGetSymbolAddress(&vh, g_VH);
    cudaGetSymbolAddress(&vl, g_VL);
    cudaGetSymbolAddress(&cx, g_CTX);

    cudaFuncSetAttribute(scores_mma, cudaFuncAttributeMaxDynamicSharedMemorySize, SMEM_DYN);
    cudaFuncSetAttribute(ctx_mma, cudaFuncAttributeMaxDynamicSharedMemorySize, SMEM_DYN);

    dim3 gproj(CH / 64, ROWS_TOT / 64);
    proj_gemm<<<gproj, 256>>>(emb, Wq, (__nv_bfloat16*)qh, (__nv_bfloat16*)ql, 1);
    proj_gemm<<<gproj, 256>>>(emb, Wk, (__nv_bfloat16*)kh, (__nv_bfloat16*)kl, 1);
    proj_gemm<<<gproj, 256>>>(emb, Wv, (__nv_bfloat16*)vh, (__nv_bfloat16*)vl, 0);

    scores_mma<<<dim3(JD / 128, CH / 128, BTOT), 256, SMEM_DYN>>>();

    zero_red_k<<<1, 32>>>();
    reduce_ss_k<<<dim3(BTOT, 64), 256>>>();
    finalize_k<<<1, 32>>>();
    softmax_k<<<BTOT * CH, 256>>>();

    ctx_mma<<<dim3(CH / 128, NSEQ / 128, BTOT), 256, SMEM_DYN>>>();

    gemm_nn<<<dim3(CDIM / 64, ROWS_TOT / 64), 256>>>((const float*)cx, Wo, outp,
                                                     ROWS_TOT, CDIM, CH);
}

// round 4
// speedup vs baseline: 2.4208x; 1.0272x over previous
#include <cuda_runtime.h>
#include <cuda_bf16.h>
#include <cstdint>
#include <cstddef>

#define NSEQ  2048
#define CDIM  64
#define CH    512
#define JD    4096
#define BTOT  16
#define ROWS_TOT (BTOT * NSEQ)
#define EPS_F 1e-5f

// stage: A 128x32 (h+l) = 16KB, B 256x32 (h+l) = 32KB
#define STAGE_BYTES 49152
#define SMEM_DYN (3 * STAGE_BYTES)

// ---------------- scratch ----------------
__device__ __nv_bfloat16 g_QtH[(size_t)BTOT * CH * NSEQ];   // [b][i][n]
__device__ __nv_bfloat16 g_QtL[(size_t)BTOT * CH * NSEQ];
__device__ __nv_bfloat16 g_KtH[(size_t)BTOT * CH * NSEQ];   // [b][j][n]
__device__ __nv_bfloat16 g_KtL[(size_t)BTOT * CH * NSEQ];
__device__ __nv_bfloat16 g_VH[(size_t)BTOT * NSEQ * CH];    // [b][n][c]
__device__ __nv_bfloat16 g_VL[(size_t)BTOT * NSEQ * CH];
__device__ float         g_S[(size_t)BTOT * CH * JD];
__device__ __nv_bfloat16 g_AH[(size_t)BTOT * CH * JD];      // attn hi [b][i][j]
__device__ __nv_bfloat16 g_AL[(size_t)BTOT * CH * JD];
__device__ float         g_CTX[(size_t)BTOT * NSEQ * CH];
__device__ double        g_red[BTOT * 2];
__device__ float         g_rstd[BTOT];

// ---------------- helpers ----------------
__device__ __forceinline__ uint32_t smem_u32(const void* p) {
    uint32_t a;
    asm("{ .reg .u64 t; cvta.to.shared.u64 t, %1; cvt.u32.u64 %0, t; }" : "=r"(a) : "l"(p));
    return a;
}
__device__ __forceinline__ void cp_async16(uint32_t s, const void* g) {
    asm volatile("cp.async.cg.shared.global [%0], [%1], 16;" :: "r"(s), "l"(g) : "memory");
}
__device__ __forceinline__ void cp_commit() {
    asm volatile("cp.async.commit_group;" ::: "memory");
}
template <int N>
__device__ __forceinline__ void cp_wait_group() {
    asm volatile("cp.async.wait_group %0;" :: "n"(N) : "memory");
}
__device__ __forceinline__ uint32_t swz(uint32_t off) {
    return off ^ ((off >> 3) & 0x30);
}
__device__ __forceinline__ uint32_t lds32(const char* base, uint32_t off) {
    return *(const uint32_t*)(base + swz(off));
}
__device__ __forceinline__ void mma16816(float* c, const uint32_t a[4],
                                         uint32_t b0, uint32_t b1) {
    asm volatile(
        "mma.sync.aligned.m16n8k16.row.col.f32.bf16.bf16.f32 "
        "{%0,%1,%2,%3}, {%4,%5,%6,%7}, {%8,%9}, {%0,%1,%2,%3};"
        : "+f"(c[0]), "+f"(c[1]), "+f"(c[2]), "+f"(c[3])
        : "r"(a[0]), "r"(a[1]), "r"(a[2]), "r"(a[3]), "r"(b0), "r"(b1));
}

// load ROWS x 32 bf16 tile (64B rows) into SW64-swizzled smem
template <int ROWS>
__device__ __forceinline__ void ldtile(uint32_t sdst, const char* g, size_t stride, int tid) {
#pragma unroll
    for (int t = 0; t < ROWS / 64; t++) {
        int op = tid + t * 256;
        int row = op >> 2, c = op & 3;
        uint32_t off = row * 64 + c * 16;
        cp_async16(sdst + swz(off), g + (size_t)row * stride + c * 16);
    }
}

// ============================================================================
// split-bf16 compute for one k32 stage; warp tile 64x64 (4 mt x 8 nt)
// stage layout: Ah @0 (8KB), Al @8KB, Bh @16KB (16KB), Bl @32KB
// ============================================================================
__device__ __forceinline__ void compute_stage(const char* stage, int wm, int wn,
                                              int g, int tg, float acc[4][8][4]) {
    const char* Ah = stage;
    const char* Al = stage + 8192;
    const char* Bh = stage + 16384;
    const char* Bl = stage + 32768;
#pragma unroll
    for (int kk2 = 0; kk2 < 2; kk2++) {
        int kb = kk2 * 32 + tg * 4;
        uint32_t ah[4][4], al[4][4];
#pragma unroll
        for (int mt = 0; mt < 4; mt++) {
            uint32_t r0 = (uint32_t)(wm + mt * 16 + g) * 64;
            uint32_t r1 = r0 + 8 * 64;
            ah[mt][0] = lds32(Ah, r0 + kb);      ah[mt][1] = lds32(Ah, r1 + kb);
            ah[mt][2] = lds32(Ah, r0 + kb + 16); ah[mt][3] = lds32(Ah, r1 + kb + 16);
            al[mt][0] = lds32(Al, r0 + kb);      al[mt][1] = lds32(Al, r1 + kb);
            al[mt][2] = lds32(Al, r0 + kb + 16); al[mt][3] = lds32(Al, r1 + kb + 16);
        }
#pragma unroll
        for (int nt = 0; nt < 8; nt++) {
            uint32_t rb = (uint32_t)(wn + nt * 8 + g) * 64;
            uint32_t bh0 = lds32(Bh, rb + kb), bh1 = lds32(Bh, rb + kb + 16);
            uint32_t bl0 = lds32(Bl, rb + kb), bl1 = lds32(Bl, rb + kb + 16);
#pragma unroll
            for (int mt = 0; mt < 4; mt++) {
                mma16816(acc[mt][nt], ah[mt], bh0, bh1);
                mma16816(acc[mt][nt], al[mt], bh0, bh1);
                mma16816(acc[mt][nt], ah[mt], bl0, bl1);
            }
        }
    }
}

// ============================================================================
// scores: S[ob][i][j] = sum_n Qt[ob][i][n] * Kt[kvb][jc][n]
// CTA tile 128(i) x 256(j), grid (JD/256=16, CH/128=4, 16), block 256
// ============================================================================
__global__ void __launch_bounds__(256, 1) scores_mma() {
    extern __shared__ char dsm[];
    uint32_t sb = smem_u32(dsm);

    int ob = blockIdx.z;
    int kvbase = (ob < 8) ? 8 : 0;
    int i0 = blockIdx.y << 7;
    int j0 = blockIdx.x << 8;
    int kvb = kvbase + (j0 >> 9);
    int jc0 = j0 & 511;

    int tid = threadIdx.x;
    int wid = tid >> 5, lane = tid & 31;
    int g = lane >> 2, tg = lane & 3;
    int wm = (wid & 1) * 64, wn = (wid >> 1) * 64;

    const char* AhB = (const char*)g_QtH + ((size_t)ob * CH + i0) * NSEQ * 2;
    const char* AlB = (const char*)g_QtL + ((size_t)ob * CH + i0) * NSEQ * 2;
    const char* BhB = (const char*)g_KtH + ((size_t)kvb * CH + jc0) * NSEQ * 2;
    const char* BlB = (const char*)g_KtL + ((size_t)kvb * CH + jc0) * NSEQ * 2;
    const size_t st = NSEQ * 2;

    float acc[4][8][4];
#pragma unroll
    for (int a = 0; a < 4; a++)
#pragma unroll
        for (int b = 0; b < 8; b++)
#pragma unroll
            for (int c = 0; c < 4; c++) acc[a][b][c] = 0.f;

    const int NCH = NSEQ / 32;   // 64

    auto load_chunk = [&](int c, int stg) {
        uint32_t s = sb + stg * STAGE_BYTES;
        size_t ko = (size_t)c * 64;
        ldtile<128>(s,         AhB + ko, st, tid);
        ldtile<128>(s + 8192,  AlB + ko, st, tid);
        ldtile<256>(s + 16384, BhB + ko, st, tid);
        ldtile<256>(s + 32768, BlB + ko, st, tid);
        cp_commit();
    };

    load_chunk(0, 0);
    load_chunk(1, 1);
    for (int c = 0; c < NCH; c++) {
        if (c + 2 < NCH) { load_chunk(c + 2, (c + 2) % 3); cp_wait_group<2>(); }
        else if (c + 1 < NCH) cp_wait_group<1>();
        else cp_wait_group<0>();
        __syncthreads();
        compute_stage(dsm + (c % 3) * STAGE_BYTES, wm, wn, g, tg, acc);
        __syncthreads();
    }

    float* gout = g_S + (size_t)ob * CH * JD;
#pragma unroll
    for (int mt = 0; mt < 4; mt++) {
#pragma unroll
        for (int nt = 0; nt < 8; nt++) {
            int row = i0 + wm + mt * 16 + g;
            int col = j0 + wn + nt * 8 + tg * 2;
            *(float2*)&gout[(size_t)row * JD + col] =
                make_float2(acc[mt][nt][0], acc[mt][nt][1]);
            *(float2*)&gout[(size_t)(row + 8) * JD + col] =
                make_float2(acc[mt][nt][2], acc[mt][nt][3]);
        }
    }
}

// ============================================================================
// ctx: CTX[ob][n][i] = sum_j V[kvb(j)][n][jc] * attn[ob][i][j]
// CTA tile 128(n) x 256(i), grid (CH/256=2, NSEQ/128=16, 16), block 256
// ============================================================================
__global__ void __launch_bounds__(256, 1) ctx_mma() {
    extern __shared__ char dsm[];
    uint32_t sb = smem_u32(dsm);

    int ob = blockIdx.z;
    int kvbase = (ob < 8) ? 8 : 0;
    int i0 = blockIdx.x << 8;
    int n0 = blockIdx.y << 7;

    int tid = threadIdx.x;
    int wid = tid >> 5, lane = tid & 31;
    int g = lane >> 2, tg = lane & 3;
    int wm = (wid & 1) * 64, wn = (wid >> 1) * 64;

    const char* BhB = (const char*)g_AH + ((size_t)ob * CH + i0) * JD * 2;
    const char* BlB = (const char*)g_AL + ((size_t)ob * CH + i0) * JD * 2;

    float acc[4][8][4];
#pragma unroll
    for (int a = 0; a < 4; a++)
#pragma unroll
        for (int b = 0; b < 8; b++)
#pragma unroll
            for (int c = 0; c < 4; c++) acc[a][b][c] = 0.f;

    const int NCH = JD / 32;   // 128

    auto load_chunk = [&](int c, int stg) {
        uint32_t s = sb + stg * STAGE_BYTES;
        int j0c = c * 32;
        int kvb = kvbase + (j0c >> 9);
        int jc0 = j0c & 511;
        const char* Ahp = (const char*)g_VH + (((size_t)kvb * NSEQ + n0) * CH + jc0) * 2;
        const char* Alp = (const char*)g_VL + (((size_t)kvb * NSEQ + n0) * CH + jc0) * 2;
        ldtile<128>(s,         Ahp, CH * 2, tid);
        ldtile<128>(s + 8192,  Alp, CH * 2, tid);
        ldtile<256>(s + 16384, BhB + (size_t)j0c * 2, JD * 2, tid);
        ldtile<256>(s + 32768, BlB + (size_t)j0c * 2, JD * 2, tid);
        cp_commit();
    };

    load_chunk(0, 0);
    load_chunk(1, 1);
    for (int c = 0; c < NCH; c++) {
        if (c + 2 < NCH) { load_chunk(c + 2, (c + 2) % 3); cp_wait_group<2>(); }
        else if (c + 1 < NCH) cp_wait_group<1>();
        else cp_wait_group<0>();
        __syncthreads();
        compute_stage(dsm + (c % 3) * STAGE_BYTES, wm, wn, g, tg, acc);
        __syncthreads();
    }

    float* gout = g_CTX + (size_t)ob * NSEQ * CH;
#pragma unroll
    for (int mt = 0; mt < 4; mt++) {
#pragma unroll
        for (int nt = 0; nt < 8; nt++) {
            int row = n0 + wm + mt * 16 + g;
            int col = i0 + wn + nt * 8 + tg * 2;
            *(float2*)&gout[(size_t)row * CH + col] =
                make_float2(acc[mt][nt][0], acc[mt][nt][1]);
            *(float2*)&gout[(size_t)(row + 8) * CH + col] =
                make_float2(acc[mt][nt][2], acc[mt][nt][3]);
        }
    }
}

// ============================================================================
// projection GEMM: C = A[32768,64] @ B[64,512]; epilogue splits to bf16 hi/lo.
// transposed=1 -> out[b][col][n], else out[m][col].
// ============================================================================
__global__ void __launch_bounds__(256) proj_gemm(const float* __restrict__ A,
                                                 const float* __restrict__ Bm,
                                                 __nv_bfloat16* __restrict__ OH,
                                                 __nv_bfloat16* __restrict__ OL,
                                                 int transposed) {
    __shared__ __align__(16) float As[16][68];
    __shared__ __align__(16) float Bs[16][64];
    const int K = CDIM, N = CH;
    int bm = blockIdx.y * 64, bn = blockIdx.x * 64;
    int tid = threadIdx.x;
    int tx = tid & 15, ty = tid >> 4;
    int am = tid >> 2, ak = (tid & 3) << 2;
    int br = tid >> 4, bc = (tid & 15) << 2;
    const float* Aptr = A + (size_t)(bm + am) * K + ak;

    float acc[4][4];
#pragma unroll
    for (int i = 0; i < 4; i++)
#pragma unroll
        for (int j = 0; j < 4; j++) acc[i][j] = 0.f;

    for (int k0 = 0; k0 < K; k0 += 16) {
        float4 av = *(const float4*)(Aptr + k0);
        As[ak + 0][am] = av.x; As[ak + 1][am] = av.y;
        As[ak + 2][am] = av.z; As[ak + 3][am] = av.w;
        *(float4*)&Bs[br][bc] = *(const float4*)&Bm[(size_t)(k0 + br) * N + bn + bc];
        __syncthreads();
#pragma unroll
        for (int kk = 0; kk < 16; kk++) {
            float a0 = As[kk][ty * 4 + 0], a1 = As[kk][ty * 4 + 1];
            float a2 = As[kk][ty * 4 + 2], a3 = As[kk][ty * 4 + 3];
            float b0 = Bs[kk][tx * 4 + 0], b1 = Bs[kk][tx * 4 + 1];
            float b2 = Bs[kk][tx * 4 + 2], b3 = Bs[kk][tx * 4 + 3];
            acc[0][0] += a0 * b0; acc[0][1] += a0 * b1; acc[0][2] += a0 * b2; acc[0][3] += a0 * b3;
            acc[1][0] += a1 * b0; acc[1][1] += a1 * b1; acc[1][2] += a1 * b2; acc[1][3] += a1 * b3;
            acc[2][0] += a2 * b0; acc[2][1] += a2 * b1; acc[2][2] += a2 * b2; acc[2][3] += a2 * b3;
            acc[3][0] += a3 * b0; acc[3][1] += a3 * b1; acc[3][2] += a3 * b2; acc[3][3] += a3 * b3;
        }
        __syncthreads();
    }

    if (transposed) {
        int b = bm >> 11;
        int nloc = (bm & 2047) + ty * 4;
#pragma unroll
        for (int j = 0; j < 4; j++) {
            int col = bn + tx * 4 + j;
            union { __nv_bfloat16 v[4]; uint2 u; } ph, pl;
#pragma unroll
            for (int i = 0; i < 4; i++) {
                float f = acc[i][j];
                __nv_bfloat16 h = __float2bfloat16(f);
                ph.v[i] = h;
                pl.v[i] = __float2bfloat16(f - __bfloat162float(h));
            }
            size_t off = (size_t)b * (CH * NSEQ) + (size_t)col * NSEQ + nloc;
            *(uint2*)&OH[off] = ph.u;
            *(uint2*)&OL[off] = pl.u;
        }
    } else {
#pragma unroll
        for (int i = 0; i < 4; i++) {
            int m = bm + ty * 4 + i;
            union { __nv_bfloat16 v[4]; uint2 u; } ph, pl;
#pragma unroll
            for (int j = 0; j < 4; j++) {
                float f = acc[i][j];
                __nv_bfloat16 h = __float2bfloat16(f);
                ph.v[j] = h;
                pl.v[j] = __float2bfloat16(f - __bfloat162float(h));
            }
            size_t off = (size_t)m * CH + bn + tx * 4;
            *(uint2*)&OH[off] = ph.u;
            *(uint2*)&OL[off] = pl.u;
        }
    }
}

// ============================================================================
// fp32 NN GEMM (out projection)
// ============================================================================
__global__ void __launch_bounds__(256) gemm_nn(const float* __restrict__ A,
                                               const float* __restrict__ Bm,
                                               float* __restrict__ Cm,
                                               int M, int N, int K) {
    __shared__ __align__(16) float As[16][68];
    __shared__ __align__(16) float Bs[16][64];
    int bm = blockIdx.y * 64, bn = blockIdx.x * 64;
    int tid = threadIdx.x;
    int tx = tid & 15, ty = tid >> 4;
    int am = tid >> 2, ak = (tid & 3) << 2;
    int br = tid >> 4, bc = (tid & 15) << 2;
    const float* Aptr = A + (size_t)(bm + am) * K + ak;

    float acc[4][4];
#pragma unroll
    for (int i = 0; i < 4; i++)
#pragma unroll
        for (int j = 0; j < 4; j++) acc[i][j] = 0.f;

    for (int k0 = 0; k0 < K; k0 += 16) {
        float4 av = *(const float4*)(Aptr + k0);
        As[ak + 0][am] = av.x; As[ak + 1][am] = av.y;
        As[ak + 2][am] = av.z; As[ak + 3][am] = av.w;
        *(float4*)&Bs[br][bc] = *(const float4*)&Bm[(size_t)(k0 + br) * N + bn + bc];
        __syncthreads();
#pragma unroll
        for (int kk = 0; kk < 16; kk++) {
            float a0 = As[kk][ty * 4 + 0], a1 = As[kk][ty * 4 + 1];
            float a2 = As[kk][ty * 4 + 2], a3 = As[kk][ty * 4 + 3];
            float b0 = Bs[kk][tx * 4 + 0], b1 = Bs[kk][tx * 4 + 1];
            float b2 = Bs[kk][tx * 4 + 2], b3 = Bs[kk][tx * 4 + 3];
            acc[0][0] += a0 * b0; acc[0][1] += a0 * b1; acc[0][2] += a0 * b2; acc[0][3] += a0 * b3;
            acc[1][0] += a1 * b0; acc[1][1] += a1 * b1; acc[1][2] += a1 * b2; acc[1][3] += a1 * b3;
            acc[2][0] += a2 * b0; acc[2][1] += a2 * b1; acc[2][2] += a2 * b2; acc[2][3] += a2 * b3;
            acc[3][0] += a3 * b0; acc[3][1] += a3 * b1; acc[3][2] += a3 * b2; acc[3][3] += a3 * b3;
        }
        __syncthreads();
    }
#pragma unroll
    for (int i = 0; i < 4; i++) {
        float4 v = make_float4(acc[i][0], acc[i][1], acc[i][2], acc[i][3]);
        *(float4*)&Cm[(size_t)(bm + ty * 4 + i) * N + bn + tx * 4] = v;
    }
}

// ============================================================================
// instance-norm stats + softmax
// ============================================================================
__global__ void zero_red_k() {
    int t = threadIdx.x;
    if (t < BTOT) { g_red[2 * t] = 0.0; g_red[2 * t + 1] = 0.0; }
}

__global__ void __launch_bounds__(256) reduce_ss_k() {
    int b = blockIdx.x;
    int chunk = blockIdx.y;
    const float* p = g_S + (size_t)b * CH * JD + (size_t)chunk * 32768;
    double s = 0.0, s2 = 0.0;
    for (int i = threadIdx.x * 4; i < 32768; i += 1024) {
        float4 v = *(const float4*)&p[i];
        s  += (double)v.x + (double)v.y + (double)v.z + (double)v.w;
        s2 += (double)v.x * v.x + (double)v.y * v.y
            + (double)v.z * v.z + (double)v.w * v.w;
    }
    for (int off = 16; off > 0; off >>= 1) {
        s  += __shfl_down_sync(0xffffffffu, s, off);
        s2 += __shfl_down_sync(0xffffffffu, s2, off);
    }
    __shared__ double ws[8], ws2[8];
    int lane = threadIdx.x & 31, wid = threadIdx.x >> 5;
    if (lane == 0) { ws[wid] = s; ws2[wid] = s2; }
    __syncthreads();
    if (threadIdx.x == 0) {
        double ts = 0.0, ts2 = 0.0;
        for (int w = 0; w < 8; w++) { ts += ws[w]; ts2 += ws2[w]; }
        atomicAdd(&g_red[2 * b], ts);
        atomicAdd(&g_red[2 * b + 1], ts2);
    }
}

__global__ void finalize_k() {
    int t = threadIdx.x;
    if (t < BTOT) {
        double n = (double)CH * (double)JD;
        double mean = g_red[2 * t] / n;
        double var  = g_red[2 * t + 1] / n - mean * mean;
        g_rstd[t] = rsqrtf((float)var + EPS_F);
    }
}

__global__ void __launch_bounds__(256) softmax_k() {
    int row = blockIdx.x;
    int b = row >> 9;
    float rstd = g_rstd[b];
    const float* p = g_S + (size_t)row * JD;
    __nv_bfloat16* ah = g_AH + (size_t)row * JD;
    __nv_bfloat16* al = g_AL + (size_t)row * JD;
    int t = threadIdx.x;

    float x[16];
    float mx = -1e30f;
#pragma unroll
    for (int u = 0; u < 16; u++) {
        x[u] = p[u * 256 + t] * rstd;
        mx = fmaxf(mx, x[u]);
    }
    __shared__ float red[8];
    for (int off = 16; off > 0; off >>= 1)
        mx = fmaxf(mx, __shfl_xor_sync(0xffffffffu, mx, off));
    int lane = t & 31, wid = t >> 5;
    if (lane == 0) red[wid] = mx;
    __syncthreads();
    float gm = red[0];
#pragma unroll
    for (int w = 1; w < 8; w++) gm = fmaxf(gm, red[w]);
    __syncthreads();

    float sum = 0.f;
#pragma unroll
    for (int u = 0; u < 16; u++) {
        x[u] = __expf(x[u] - gm);
        sum += x[u];
    }
    for (int off = 16; off > 0; off >>= 1)
        sum += __shfl_xor_sync(0xffffffffu, sum, off);
    if (lane == 0) red[wid] = sum;
    __syncthreads();
    float tot = 0.f;
#pragma unroll
    for (int w = 0; w < 8; w++) tot += red[w];
    float inv = 1.0f / tot;
#pragma unroll
    for (int u = 0; u < 16; u++) {
        float f = x[u] * inv;
        __nv_bfloat16 h = __float2bfloat16(f);
        ah[u * 256 + t] = h;
        al[u * 256 + t] = __float2bfloat16(f - __bfloat162float(h));
    }
}

// ============================================================================
// launch
// ============================================================================
extern "C" void kernel_launch(void* const* d_in, const int* in_sizes, int n_in,
                              void* d_out, int out_size) {
    const float* emb = (const float*)d_in[0];
    const float* Wq  = (const float*)d_in[1];
    const float* Wk  = (const float*)d_in[2];
    const float* Wv  = (const float*)d_in[3];
    const float* Wo  = (const float*)d_in[4];
    float* outp = (float*)d_out;

    void *qh, *ql, *kh, *kl, *vh, *vl, *cx;
    cudaGetSymbolAddress(&qh, g_QtH);
    cudaGetSymbolAddress(&ql, g_QtL);
    cudaGetSymbolAddress(&kh, g_KtH);
    cudaGetSymbolAddress(&kl, g_KtL);
    cudaGetSymbolAddress(&vh, g_VH);
    cudaGetSymbolAddress(&vl, g_VL);
    cudaGetSymbolAddress(&cx, g_CTX);

    cudaFuncSetAttribute(scores_mma, cudaFuncAttributeMaxDynamicSharedMemorySize, SMEM_DYN);
    cudaFuncSetAttribute(ctx_mma, cudaFuncAttributeMaxDynamicSharedMemorySize, SMEM_DYN);

    dim3 gproj(CH / 64, ROWS_TOT / 64);
    proj_gemm<<<gproj, 256>>>(emb, Wq, (__nv_bfloat16*)qh, (__nv_bfloat16*)ql, 1);
    proj_gemm<<<gproj, 256>>>(emb, Wk, (__nv_bfloat16*)kh, (__nv_bfloat16*)kl, 1);
    proj_gemm<<<gproj, 256>>>(emb, Wv, (__nv_bfloat16*)vh, (__nv_bfloat16*)vl, 0);

    scores_mma<<<dim3(JD / 256, CH / 128, BTOT), 256, SMEM_DYN>>>();

    zero_red_k<<<1, 32>>>();
    reduce_ss_k<<<dim3(BTOT, 64), 256>>>();
    finalize_k<<<1, 32>>>();
    softmax_k<<<BTOT * CH, 256>>>();

    ctx_mma<<<dim3(CH / 256, NSEQ / 128, BTOT), 256, SMEM_DYN>>>();

    gemm_nn<<<dim3(CDIM / 64, ROWS_TOT / 64), 256>>>((const float*)cx, Wo, outp,
                                                     ROWS_TOT, CDIM, CH);
}

// round 5
// speedup vs baseline: 3.7103x; 1.5327x over previous
#include <cuda_runtime.h>
#include <cuda_fp16.h>
#include <cstdint>
#include <cstddef>

#define NSEQ  2048
#define CDIM  64
#define CH    512
#define JD    4096
#define BTOT  16
#define ROWS_TOT (BTOT * NSEQ)
#define EPS_F 1e-5f
#define SCALE_F 256.0f          // operand pre-scale (2^8)

// stage (k64): A hi 128x64 fp16 =16KB, A lo 16KB, B hi 256x64 fp16 =32KB
#define STAGE_BYTES 65536
#define SMEM_DYN (3 * STAGE_BYTES)

// ---------------- scratch ----------------
__device__ __half g_QtH[(size_t)BTOT * CH * NSEQ];   // [b][i][n], x256
__device__ __half g_QtL[(size_t)BTOT * CH * NSEQ];
__device__ __half g_KtH[(size_t)BTOT * CH * NSEQ];   // [b][j][n], x256 (hi only)
__device__ __half g_VH[(size_t)BTOT * NSEQ * CH];    // [b][n][c], x256
__device__ __half g_VL[(size_t)BTOT * NSEQ * CH];
__device__ float  g_S[(size_t)BTOT * CH * JD];       // scores, x2^16
__device__ __half g_AH[(size_t)BTOT * CH * JD];      // attn fp16 [b][i][j]
__device__ float  g_CTX[(size_t)BTOT * NSEQ * CH];   // true scale
__device__ double g_red[BTOT * 2];
__device__ float  g_rstd[BTOT];                      // rsqrt(var+eps)/2^16

// ---------------- helpers ----------------
__device__ __forceinline__ uint32_t smem_u32(const void* p) {
    uint32_t a;
    asm("{ .reg .u64 t; cvta.to.shared.u64 t, %1; cvt.u32.u64 %0, t; }" : "=r"(a) : "l"(p));
    return a;
}
__device__ __forceinline__ void cp_async16(uint32_t s, const void* g) {
    asm volatile("cp.async.cg.shared.global [%0], [%1], 16;" :: "r"(s), "l"(g) : "memory");
}
__device__ __forceinline__ void cp_commit() {
    asm volatile("cp.async.commit_group;" ::: "memory");
}
template <int N>
__device__ __forceinline__ void cp_wait_group() {
    asm volatile("cp.async.wait_group %0;" :: "n"(N) : "memory");
}
// SW128 swizzle for 128-byte rows
__device__ __forceinline__ uint32_t swz(uint32_t off) {
    return off ^ ((off >> 3) & 0x70);
}
__device__ __forceinline__ uint32_t lds32(const char* base, uint32_t off) {
    return *(const uint32_t*)(base + swz(off));
}
__device__ __forceinline__ void mma16816h(float* c, const uint32_t a[4],
                                          uint32_t b0, uint32_t b1) {
    asm volatile(
        "mma.sync.aligned.m16n8k16.row.col.f32.f16.f16.f32 "
        "{%0,%1,%2,%3}, {%4,%5,%6,%7}, {%8,%9}, {%0,%1,%2,%3};"
        : "+f"(c[0]), "+f"(c[1]), "+f"(c[2]), "+f"(c[3])
        : "r"(a[0]), "r"(a[1]), "r"(a[2]), "r"(a[3]), "r"(b0), "r"(b1));
}

// load ROWS x 64 fp16 tile (128B rows) into SW128-swizzled smem
template <int ROWS>
__device__ __forceinline__ void ldtile(uint32_t sdst, const char* g, size_t stride, int tid) {
#pragma unroll
    for (int t = 0; t < ROWS / 32; t++) {
        int op = tid + t * 256;
        int row = op >> 3, c = op & 7;
        uint32_t off = row * 128 + c * 16;
        cp_async16(sdst + swz(off), g + (size_t)row * stride + c * 16);
    }
}

// ============================================================================
// 2-term fp16 compute for one k64 stage; warp tile 64x64 (4 mt x 8 nt)
// stage: Ah @0 (16KB), Al @16KB, Bh @32KB (32KB)
// ============================================================================
__device__ __forceinline__ void compute_stage(const char* stage, int wm, int wn,
                                              int g, int tg, float acc[4][8][4]) {
    const char* Ah = stage;
    const char* Al = stage + 16384;
    const char* Bh = stage + 32768;
#pragma unroll
    for (int kk = 0; kk < 4; kk++) {
        uint32_t kb = kk * 32 + tg * 4;
        uint32_t ah[4][4], al[4][4];
#pragma unroll
        for (int mt = 0; mt < 4; mt++) {
            uint32_t r0 = (uint32_t)(wm + mt * 16 + g) * 128;
            uint32_t r1 = r0 + 8 * 128;
            ah[mt][0] = lds32(Ah, r0 + kb);      ah[mt][1] = lds32(Ah, r1 + kb);
            ah[mt][2] = lds32(Ah, r0 + kb + 16); ah[mt][3] = lds32(Ah, r1 + kb + 16);
            al[mt][0] = lds32(Al, r0 + kb);      al[mt][1] = lds32(Al, r1 + kb);
            al[mt][2] = lds32(Al, r0 + kb + 16); al[mt][3] = lds32(Al, r1 + kb + 16);
        }
#pragma unroll
        for (int nt = 0; nt < 8; nt++) {
            uint32_t rb = (uint32_t)(wn + nt * 8 + g) * 128;
            uint32_t b0 = lds32(Bh, rb + kb), b1 = lds32(Bh, rb + kb + 16);
#pragma unroll
            for (int mt = 0; mt < 4; mt++) {
                mma16816h(acc[mt][nt], ah[mt], b0, b1);
                mma16816h(acc[mt][nt], al[mt], b0, b1);
            }
        }
    }
}

// ============================================================================
// scores: S[ob][i][j] = sum_n Qt[ob][i][n] * Kt[kvb][jc][n]   (x 2^16)
// CTA tile 128(i) x 256(j), grid (16, 4, 16), block 256
// Also accumulates per-batch sum / sumsq into g_red (fused instance-norm).
// ============================================================================
__global__ void __launch_bounds__(256, 1) scores_mma() {
    extern __shared__ char dsm[];
    uint32_t sb = smem_u32(dsm);
    __shared__ double sred[8], sred2[8];

    int ob = blockIdx.z;
    int kvbase = (ob < 8) ? 8 : 0;
    int i0 = blockIdx.y << 7;
    int j0 = blockIdx.x << 8;
    int kvb = kvbase + (j0 >> 9);
    int jc0 = j0 & 511;

    int tid = threadIdx.x;
    int wid = tid >> 5, lane = tid & 31;
    int g = lane >> 2, tg = lane & 3;
    int wm = (wid & 1) * 64, wn = (wid >> 1) * 64;

    const char* AhB = (const char*)g_QtH + ((size_t)ob * CH + i0) * NSEQ * 2;
    const char* AlB = (const char*)g_QtL + ((size_t)ob * CH + i0) * NSEQ * 2;
    const char* BhB = (const char*)g_KtH + ((size_t)kvb * CH + jc0) * NSEQ * 2;
    const size_t st = NSEQ * 2;

    float acc[4][8][4];
#pragma unroll
    for (int a = 0; a < 4; a++)
#pragma unroll
        for (int b = 0; b < 8; b++)
#pragma unroll
            for (int c = 0; c < 4; c++) acc[a][b][c] = 0.f;

    const int NCH = NSEQ / 64;   // 32

    auto load_chunk = [&](int c, int stg) {
        uint32_t s = sb + stg * STAGE_BYTES;
        size_t ko = (size_t)c * 128;
        ldtile<128>(s,         AhB + ko, st, tid);
        ldtile<128>(s + 16384, AlB + ko, st, tid);
        ldtile<256>(s + 32768, BhB + ko, st, tid);
        cp_commit();
    };

    load_chunk(0, 0);
    load_chunk(1, 1);
    for (int c = 0; c < NCH; c++) {
        if (c + 2 < NCH) { load_chunk(c + 2, (c + 2) % 3); cp_wait_group<2>(); }
        else if (c + 1 < NCH) cp_wait_group<1>();
        else cp_wait_group<0>();
        __syncthreads();
        compute_stage(dsm + (c % 3) * STAGE_BYTES, wm, wn, g, tg, acc);
        __syncthreads();
    }

    // write scores + fused sum/sumsq
    float* gout = g_S + (size_t)ob * CH * JD;
    float s1 = 0.f, s2 = 0.f;
#pragma unroll
    for (int mt = 0; mt < 4; mt++) {
#pragma unroll
        for (int nt = 0; nt < 8; nt++) {
            int row = i0 + wm + mt * 16 + g;
            int col = j0 + wn + nt * 8 + tg * 2;
            float v0 = acc[mt][nt][0], v1 = acc[mt][nt][1];
            float v2 = acc[mt][nt][2], v3 = acc[mt][nt][3];
            *(float2*)&gout[(size_t)row * JD + col] = make_float2(v0, v1);
            *(float2*)&gout[(size_t)(row + 8) * JD + col] = make_float2(v2, v3);
            s1 += v0 + v1 + v2 + v3;
            s2 += v0 * v0 + v1 * v1 + v2 * v2 + v3 * v3;
        }
    }
    double d1 = (double)s1, d2 = (double)s2;
    for (int off = 16; off > 0; off >>= 1) {
        d1 += __shfl_down_sync(0xffffffffu, d1, off);
        d2 += __shfl_down_sync(0xffffffffu, d2, off);
    }
    if (lane == 0) { sred[wid] = d1; sred2[wid] = d2; }
    __syncthreads();
    if (tid == 0) {
        double t1 = 0.0, t2 = 0.0;
#pragma unroll
        for (int w = 0; w < 8; w++) { t1 += sred[w]; t2 += sred2[w]; }
        atomicAdd(&g_red[2 * ob], t1);
        atomicAdd(&g_red[2 * ob + 1], t2);
    }
}

// ============================================================================
// ctx: CTX[ob][n][i] = sum_j V[kvb(j)][n][jc] * attn[ob][i][j]
// CTA tile 128(n) x 256(i), grid (2, 16, 16), block 256
// ============================================================================
__global__ void __launch_bounds__(256, 1) ctx_mma() {
    extern __shared__ char dsm[];
    uint32_t sb = smem_u32(dsm);

    int ob = blockIdx.z;
    int kvbase = (ob < 8) ? 8 : 0;
    int i0 = blockIdx.x << 8;
    int n0 = blockIdx.y << 7;

    int tid = threadIdx.x;
    int wid = tid >> 5, lane = tid & 31;
    int g = lane >> 2, tg = lane & 3;
    int wm = (wid & 1) * 64, wn = (wid >> 1) * 64;

    const char* BhB = (const char*)g_AH + ((size_t)ob * CH + i0) * JD * 2;

    float acc[4][8][4];
#pragma unroll
    for (int a = 0; a < 4; a++)
#pragma unroll
        for (int b = 0; b < 8; b++)
#pragma unroll
            for (int c = 0; c < 4; c++) acc[a][b][c] = 0.f;

    const int NCH = JD / 64;   // 64

    auto load_chunk = [&](int c, int stg) {
        uint32_t s = sb + stg * STAGE_BYTES;
        int j0c = c * 64;
        int kvb = kvbase + (j0c >> 9);
        int jc0 = j0c & 511;
        const char* Ahp = (const char*)g_VH + (((size_t)kvb * NSEQ + n0) * CH + jc0) * 2;
        const char* Alp = (const char*)g_VL + (((size_t)kvb * NSEQ + n0) * CH + jc0) * 2;
        ldtile<128>(s,         Ahp, CH * 2, tid);
        ldtile<128>(s + 16384, Alp, CH * 2, tid);
        ldtile<256>(s + 32768, BhB + (size_t)j0c * 2, JD * 2, tid);
        cp_commit();
    };

    load_chunk(0, 0);
    load_chunk(1, 1);
    for (int c = 0; c < NCH; c++) {
        if (c + 2 < NCH) { load_chunk(c + 2, (c + 2) % 3); cp_wait_group<2>(); }
        else if (c + 1 < NCH) cp_wait_group<1>();
        else cp_wait_group<0>();
        __syncthreads();
        compute_stage(dsm + (c % 3) * STAGE_BYTES, wm, wn, g, tg, acc);
        __syncthreads();
    }

    const float ds = 1.0f / SCALE_F;   // undo V pre-scale
    float* gout = g_CTX + (size_t)ob * NSEQ * CH;
#pragma unroll
    for (int mt = 0; mt < 4; mt++) {
#pragma unroll
        for (int nt = 0; nt < 8; nt++) {
            int row = n0 + wm + mt * 16 + g;
            int col = i0 + wn + nt * 8 + tg * 2;
            *(float2*)&gout[(size_t)row * CH + col] =
                make_float2(acc[mt][nt][0] * ds, acc[mt][nt][1] * ds);
            *(float2*)&gout[(size_t)(row + 8) * CH + col] =
                make_float2(acc[mt][nt][2] * ds, acc[mt][nt][3] * ds);
        }
    }
}

// ============================================================================
// projection GEMM: C = A[32768,64] @ B[64,512], scaled x256, split fp16 hi(/lo).
// transposed=1 -> out[b][col][n], else out[m][col]. OL may be null (hi only).
// ============================================================================
__global__ void __launch_bounds__(256) proj_gemm(const float* __restrict__ A,
                                                 const float* __restrict__ Bm,
                                                 __half* __restrict__ OH,
                                                 __half* __restrict__ OL,
                                                 int transposed) {
    __shared__ __align__(16) float As[16][68];
    __shared__ __align__(16) float Bs[16][64];
    const int K = CDIM, N = CH;
    int bm = blockIdx.y * 64, bn = blockIdx.x * 64;
    int tid = threadIdx.x;
    int tx = tid & 15, ty = tid >> 4;
    int am = tid >> 2, ak = (tid & 3) << 2;
    int br = tid >> 4, bc = (tid & 15) << 2;
    const float* Aptr = A + (size_t)(bm + am) * K + ak;

    float acc[4][4];
#pragma unroll
    for (int i = 0; i < 4; i++)
#pragma unroll
        for (int j = 0; j < 4; j++) acc[i][j] = 0.f;

    for (int k0 = 0; k0 < K; k0 += 16) {
        float4 av = *(const float4*)(Aptr + k0);
        As[ak + 0][am] = av.x; As[ak + 1][am] = av.y;
        As[ak + 2][am] = av.z; As[ak + 3][am] = av.w;
        *(float4*)&Bs[br][bc] = *(const float4*)&Bm[(size_t)(k0 + br) * N + bn + bc];
        __syncthreads();
#pragma unroll
        for (int kk = 0; kk < 16; kk++) {
            float a0 = As[kk][ty * 4 + 0], a1 = As[kk][ty * 4 + 1];
            float a2 = As[kk][ty * 4 + 2], a3 = As[kk][ty * 4 + 3];
            float b0 = Bs[kk][tx * 4 + 0], b1 = Bs[kk][tx * 4 + 1];
            float b2 = Bs[kk][tx * 4 + 2], b3 = Bs[kk][tx * 4 + 3];
            acc[0][0] += a0 * b0; acc[0][1] += a0 * b1; acc[0][2] += a0 * b2; acc[0][3] += a0 * b3;
            acc[1][0] += a1 * b0; acc[1][1] += a1 * b1; acc[1][2] += a1 * b2; acc[1][3] += a1 * b3;
            acc[2][0] += a2 * b0; acc[2][1] += a2 * b1; acc[2][2] += a2 * b2; acc[2][3] += a2 * b3;
            acc[3][0] += a3 * b0; acc[3][1] += a3 * b1; acc[3][2] += a3 * b2; acc[3][3] += a3 * b3;
        }
        __syncthreads();
    }

    if (transposed) {
        int b = bm >> 11;
        int nloc = (bm & 2047) + ty * 4;
#pragma unroll
        for (int j = 0; j < 4; j++) {
            int col = bn + tx * 4 + j;
            union { __half v[4]; uint2 u; } ph, pl;
#pragma unroll
            for (int i = 0; i < 4; i++) {
                float f = acc[i][j] * SCALE_F;
                __half h = __float2half(f);
                ph.v[i] = h;
                pl.v[i] = __float2half(f - __half2float(h));
            }
            size_t off = (size_t)b * (CH * NSEQ) + (size_t)col * NSEQ + nloc;
            *(uint2*)&OH[off] = ph.u;
            if (OL) *(uint2*)&OL[off] = pl.u;
        }
    } else {
#pragma unroll
        for (int i = 0; i < 4; i++) {
            int m = bm + ty * 4 + i;
            union { __half v[4]; uint2 u; } ph, pl;
#pragma unroll
            for (int j = 0; j < 4; j++) {
                float f = acc[i][j] * SCALE_F;
                __half h = __float2half(f);
                ph.v[j] = h;
                pl.v[j] = __float2half(f - __half2float(h));
            }
            size_t off = (size_t)m * CH + bn + tx * 4;
            *(uint2*)&OH[off] = ph.u;
            if (OL) *(uint2*)&OL[off] = pl.u;
        }
    }
}

// ============================================================================
// fp32 NN GEMM (out projection)
// ============================================================================
__global__ void __launch_bounds__(256) gemm_nn(const float* __restrict__ A,
                                               const float* __restrict__ Bm,
                                               float* __restrict__ Cm,
                                               int M, int N, int K) {
    __shared__ __align__(16) float As[16][68];
    __shared__ __align__(16) float Bs[16][64];
    int bm = blockIdx.y * 64, bn = blockIdx.x * 64;
    int tid = threadIdx.x;
    int tx = tid & 15, ty = tid >> 4;
    int am = tid >> 2, ak = (tid & 3) << 2;
    int br = tid >> 4, bc = (tid & 15) << 2;
    const float* Aptr = A + (size_t)(bm + am) * K + ak;

    float acc[4][4];
#pragma unroll
    for (int i = 0; i < 4; i++)
#pragma unroll
        for (int j = 0; j < 4; j++) acc[i][j] = 0.f;

    for (int k0 = 0; k0 < K; k0 += 16) {
        float4 av = *(const float4*)(Aptr + k0);
        As[ak + 0][am] = av.x; As[ak + 1][am] = av.y;
        As[ak + 2][am] = av.z; As[ak + 3][am] = av.w;
        *(float4*)&Bs[br][bc] = *(const float4*)&Bm[(size_t)(k0 + br) * N + bn + bc];
        __syncthreads();
#pragma unroll
        for (int kk = 0; kk < 16; kk++) {
            float a0 = As[kk][ty * 4 + 0], a1 = As[kk][ty * 4 + 1];
            float a2 = As[kk][ty * 4 + 2], a3 = As[kk][ty * 4 + 3];
            float b0 = Bs[kk][tx * 4 + 0], b1 = Bs[kk][tx * 4 + 1];
            float b2 = Bs[kk][tx * 4 + 2], b3 = Bs[kk][tx * 4 + 3];
            acc[0][0] += a0 * b0; acc[0][1] += a0 * b1; acc[0][2] += a0 * b2; acc[0][3] += a0 * b3;
            acc[1][0] += a1 * b0; acc[1][1] += a1 * b1; acc[1][2] += a1 * b2; acc[1][3] += a1 * b3;
            acc[2][0] += a2 * b0; acc[2][1] += a2 * b1; acc[2][2] += a2 * b2; acc[2][3] += a2 * b3;
            acc[3][0] += a3 * b0; acc[3][1] += a3 * b1; acc[3][2] += a3 * b2; acc[3][3] += a3 * b3;
        }
        __syncthreads();
    }
#pragma unroll
    for (int i = 0; i < 4; i++) {
        float4 v = make_float4(acc[i][0], acc[i][1], acc[i][2], acc[i][3]);
        *(float4*)&Cm[(size_t)(bm + ty * 4 + i) * N + bn + tx * 4] = v;
    }
}

// ============================================================================
// instance-norm finalize + softmax
// ============================================================================
__global__ void zero_red_k() {
    int t = threadIdx.x;
    if (t < BTOT) { g_red[2 * t] = 0.0; g_red[2 * t + 1] = 0.0; }
}

__global__ void finalize_k() {
    int t = threadIdx.x;
    if (t < BTOT) {
        const double SC = 65536.0;   // scores are scaled by 2^16
        double n = (double)CH * (double)JD;
        double mean = g_red[2 * t] / (n * SC);
        double var  = g_red[2 * t + 1] / (n * SC * SC) - mean * mean;
        g_rstd[t] = rsqrtf((float)var + EPS_F) / (float)SC;
    }
}

__global__ void __launch_bounds__(256) softmax_k() {
    int row = blockIdx.x;
    int b = row >> 9;
    float rstd = g_rstd[b];          // already includes 1/2^16
    const float* p = g_S + (size_t)row * JD;
    __half* ah = g_AH + (size_t)row * JD;
    int t = threadIdx.x;

    float x[16];
    float mx = -1e30f;
#pragma unroll
    for (int u = 0; u < 16; u++) {
        x[u] = p[u * 256 + t] * rstd;
        mx = fmaxf(mx, x[u]);
    }
    __shared__ float red[8];
    for (int off = 16; off > 0; off >>= 1)
        mx = fmaxf(mx, __shfl_xor_sync(0xffffffffu, mx, off));
    int lane = t & 31, wid = t >> 5;
    if (lane == 0) red[wid] = mx;
    __syncthreads();
    float gm = red[0];
#pragma unroll
    for (int w = 1; w < 8; w++) gm = fmaxf(gm, red[w]);
    __syncthreads();

    float sum = 0.f;
#pragma unroll
    for (int u = 0; u < 16; u++) {
        x[u] = __expf(x[u] - gm);
        sum += x[u];
    }
    for (int off = 16; off > 0; off >>= 1)
        sum += __shfl_xor_sync(0xffffffffu, sum, off);
    if (lane == 0) red[wid] = sum;
    __syncthreads();
    float tot = 0.f;
#pragma unroll
    for (int w = 0; w < 8; w++) tot += red[w];
    float inv = 1.0f / tot;
#pragma unroll
    for (int u = 0; u < 16; u++)
        ah[u * 256 + t] = __float2half(x[u] * inv);
}

// ============================================================================
// launch
// ============================================================================
extern "C" void kernel_launch(void* const* d_in, const int* in_sizes, int n_in,
                              void* d_out, int out_size) {
    const float* emb = (const float*)d_in[0];
    const float* Wq  = (const float*)d_in[1];
    const float* Wk  = (const float*)d_in[2];
    const float* Wv  = (const float*)d_in[3];
    const float* Wo  = (const float*)d_in[4];
    float* outp = (float*)d_out;

    void *qh, *ql, *kh, *vh, *vl, *cx;
    cudaGetSymbolAddress(&qh, g_QtH);
    cudaGetSymbolAddress(&ql, g_QtL);
    cudaGetSymbolAddress(&kh, g_KtH);
    cudaGetSymbolAddress(&vh, g_VH);
    cudaGetSymbolAddress(&vl, g_VL);
    cudaGetSymbolAddress(&cx, g_CTX);

    cudaFuncSetAttribute(scores_mma, cudaFuncAttributeMaxDynamicSharedMemorySize, SMEM_DYN);
    cudaFuncSetAttribute(ctx_mma, cudaFuncAttributeMaxDynamicSharedMemorySize, SMEM_DYN);

    dim3 gproj(CH / 64, ROWS_TOT / 64);
    proj_gemm<<<gproj, 256>>>(emb, Wq, (__half*)qh, (__half*)ql, 1);
    proj_gemm<<<gproj, 256>>>(emb, Wk, (__half*)kh, (__half*)nullptr, 1);
    proj_gemm<<<gproj, 256>>>(emb, Wv, (__half*)vh, (__half*)vl, 0);

    zero_red_k<<<1, 32>>>();
    scores_mma<<<dim3(JD / 256, CH / 128, BTOT), 256, SMEM_DYN>>>();
    finalize_k<<<1, 32>>>();
    softmax_k<<<BTOT * CH, 256>>>();

    ctx_mma<<<dim3(CH / 256, NSEQ / 128, BTOT), 256, SMEM_DYN>>>();

    gemm_nn<<<dim3(CDIM / 64, ROWS_TOT / 64), 256>>>((const float*)cx, Wo, outp,
                                                     ROWS_TOT, CDIM, CH);
}